// round 15
// baseline (speedup 1.0000x reference)
#include <cuda_runtime.h>
#include <cuda_bf16.h>
#include <math.h>
#include <stdint.h>

#define BSZ 256
#define N0 1024
#define N1 2048
#define N2 1024
#define N3 512
#define TT 16
#define KC 320          // Eigen MT gebp depth-blocking (validated bit-exact R7-R14)
#define MB (TT * BSZ)   // 4096 batched rows

// ------------------------- device scratch (static) -------------------------
__device__ __align__(16) float g_I0p[4 * BSZ * N1];   // I0 panel partials (layer0 only)
__device__ __align__(16) float g_s0[MB * N1];         // spikes L0, all steps
__device__ __align__(16) float g_c1[MB * N2];         // L1 currents
__device__ __align__(16) float g_s1[MB * N2];         // spikes L1, all steps
__device__ __align__(16) float g_c2[MB * N3];         // L2 currents
__device__ float g_wn0[N1], g_wn1[N2], g_wn2[N3];
__device__ double g_cost;
__device__ unsigned int g_tot;

// ------------------------- f32x2 packed helpers ----------------------------
__device__ __forceinline__ unsigned long long f2pack(float x, float y) {
    unsigned long long r;
    asm("mov.b64 %0, {%1, %2};" : "=l"(r) : "f"(x), "f"(y));
    return r;
}
__device__ __forceinline__ void f2fma(unsigned long long& d,
                                      unsigned long long a, unsigned long long b) {
    asm("fma.rn.f32x2 %0, %1, %2, %0;" : "+l"(d) : "l"(a), "l"(b));
}
__device__ __forceinline__ void f2add(unsigned long long& d, unsigned long long a) {
    asm("add.rn.f32x2 %0, %1, %0;" : "+l"(d) : "l"(a));
}
__device__ __forceinline__ void f2unpack(float& x, float& y, unsigned long long v) {
    asm("mov.b64 {%0, %1}, %2;" : "=f"(x), "=f"(y) : "l"(v));
}

// ------------------------------- init --------------------------------------
__global__ void init_k() {
    if (threadIdx.x == 0) { g_cost = 0.0; g_tot = 0u; }
}

// ---- per-row weight norms: warp per row, coalesced, tree reduce ------------
__global__ void wnorm_k(const float* __restrict__ w, int K, int Nrows,
                        float* __restrict__ o) {
    int row = blockIdx.x * 8 + (threadIdx.x >> 5);
    int lane = threadIdx.x & 31;
    if (row >= Nrows) return;
    const float* wr = w + (size_t)row * K;
    float s = 0.f;
    for (int j = lane; j < K; j += 32) {
        float v = wr[j];
        s = __fadd_rn(s, __fmul_rn(v, v));
    }
    #pragma unroll
    for (int off = 16; off; off >>= 1)
        s = __fadd_rn(s, __shfl_down_sync(0xffffffffu, s, off));
    if (lane == 0) o[row] = sqrtf(s);
}

// -------------------- GEMM, split-K form (layer-0 only) ---------------------
// Validated R9-R14. P[z,m,n] = strict ascending-k FMA chain over panel z.
__global__ void __launch_bounds__(256) gemm0_k(const float* __restrict__ A,
                                               const float* __restrict__ Bm,
                                               float* __restrict__ P,
                                               int M, int N, int K) {
    __shared__ float As[16][68];
    __shared__ float Bs[16][68];
    const int bn0 = blockIdx.x * 64, bm0 = blockIdx.y * 64;
    const int k0 = blockIdx.z * KC;
    const int kchunk = min(KC, K - k0);
    const int tid = threadIdx.x;
    const int tx = tid & 31, ty = tid >> 5;
    const float* Ag = A + (size_t)bm0 * K + k0;
    const float* Bg = Bm + (size_t)bn0 * K + k0;

    unsigned long long acc2[4][2];
    #pragma unroll
    for (int p = 0; p < 4; p++) { acc2[p][0] = 0ull; acc2[p][1] = 0ull; }

    const int arow = tid >> 2, akq = (tid & 3) * 4;
    float4 ra = *(const float4*)(Ag + (size_t)arow * K + akq);
    float4 rb = *(const float4*)(Bg + (size_t)arow * K + akq);

    for (int kt = 0; kt < kchunk; kt += 16) {
        As[akq + 0][arow] = ra.x; As[akq + 1][arow] = ra.y;
        As[akq + 2][arow] = ra.z; As[akq + 3][arow] = ra.w;
        Bs[akq + 0][arow] = rb.x; Bs[akq + 1][arow] = rb.y;
        Bs[akq + 2][arow] = rb.z; Bs[akq + 3][arow] = rb.w;
        __syncthreads();
        int kn = kt + 16;
        if (kn < kchunk) {
            ra = *(const float4*)(Ag + (size_t)arow * K + kn + akq);
            rb = *(const float4*)(Bg + (size_t)arow * K + kn + akq);
        }
        #pragma unroll
        for (int k = 0; k < 16; k++) {
            float2 b = *(const float2*)&Bs[k][tx * 2];
            unsigned long long bb0 = f2pack(b.x, b.x);
            unsigned long long bb1 = f2pack(b.y, b.y);
            const ulonglong2* ap = (const ulonglong2*)&As[k][ty * 8];
            ulonglong2 a01 = ap[0];
            ulonglong2 a23 = ap[1];
            f2fma(acc2[0][0], a01.x, bb0); f2fma(acc2[0][1], a01.x, bb1);
            f2fma(acc2[1][0], a01.y, bb0); f2fma(acc2[1][1], a01.y, bb1);
            f2fma(acc2[2][0], a23.x, bb0); f2fma(acc2[2][1], a23.x, bb1);
            f2fma(acc2[3][0], a23.y, bb0); f2fma(acc2[3][1], a23.y, bb1);
        }
        __syncthreads();
    }
    float* Pg = P + (size_t)blockIdx.z * M * N + (size_t)bm0 * N + bn0;
    #pragma unroll
    for (int p = 0; p < 4; p++) {
        float r0c0, r1c0, r0c1, r1c1;
        f2unpack(r0c0, r1c0, acc2[p][0]);
        f2unpack(r0c1, r1c1, acc2[p][1]);
        *(float2*)&Pg[(size_t)(ty * 8 + 2 * p) * N + tx * 2] = make_float2(r0c0, r0c1);
        *(float2*)&Pg[(size_t)(ty * 8 + 2 * p + 1) * N + tx * 2] = make_float2(r1c0, r1c1);
    }
}

// ---- GEMM, full-K, kc=320 panels, 2-stage smem, BK=32 ----------------------
// Same accumulation order and inner-loop body as R14 (bit-validated); the
// only change is BK 16->32: compute window per prefetch doubles (~340 cyc),
// covering L2 latency (~250 cyc) that R14 left exposed.
__global__ void __launch_bounds__(256) gemmf_k(const float* __restrict__ A,
                                               const float* __restrict__ Bm,
                                               float* __restrict__ C,
                                               int M, int N, int K) {
    __shared__ float As[2][32][68];
    __shared__ float Bs[2][32][68];

    const int bn0 = blockIdx.x * 64, bm0 = blockIdx.y * 64;
    const int tid = threadIdx.x;
    const int tx = tid & 31, ty = tid >> 5;      // 32 n-groups, 8 m-groups

    const float* Ag = A + (size_t)bm0 * K;
    const float* Bg = Bm + (size_t)bn0 * K;

    unsigned long long acc2[4][2], tot2[4][2];
    #pragma unroll
    for (int p = 0; p < 4; p++) {
        acc2[p][0] = 0ull; acc2[p][1] = 0ull;
        tot2[p][0] = 0ull; tot2[p][1] = 0ull;
    }

    const int arow = tid >> 2, akq = (tid & 3) * 4;
    float4 ra0 = *(const float4*)(Ag + (size_t)arow * K + akq);
    float4 ra1 = *(const float4*)(Ag + (size_t)arow * K + akq + 16);
    float4 rb0 = *(const float4*)(Bg + (size_t)arow * K + akq);
    float4 rb1 = *(const float4*)(Bg + (size_t)arow * K + akq + 16);

    int buf = 0;
    for (int kt = 0; kt < K; kt += 32) {
        As[buf][akq + 0][arow] = ra0.x; As[buf][akq + 1][arow] = ra0.y;
        As[buf][akq + 2][arow] = ra0.z; As[buf][akq + 3][arow] = ra0.w;
        As[buf][akq + 16][arow] = ra1.x; As[buf][akq + 17][arow] = ra1.y;
        As[buf][akq + 18][arow] = ra1.z; As[buf][akq + 19][arow] = ra1.w;
        Bs[buf][akq + 0][arow] = rb0.x; Bs[buf][akq + 1][arow] = rb0.y;
        Bs[buf][akq + 2][arow] = rb0.z; Bs[buf][akq + 3][arow] = rb0.w;
        Bs[buf][akq + 16][arow] = rb1.x; Bs[buf][akq + 17][arow] = rb1.y;
        Bs[buf][akq + 18][arow] = rb1.z; Bs[buf][akq + 19][arow] = rb1.w;
        __syncthreads();                 // single barrier per k-tile
        int kn = kt + 32;
        if (kn < K) {                    // next-tile loads fly during compute
            ra0 = *(const float4*)(Ag + (size_t)arow * K + kn + akq);
            ra1 = *(const float4*)(Ag + (size_t)arow * K + kn + akq + 16);
            rb0 = *(const float4*)(Bg + (size_t)arow * K + kn + akq);
            rb1 = *(const float4*)(Bg + (size_t)arow * K + kn + akq + 16);
        }
        #pragma unroll
        for (int k = 0; k < 32; k++) {
            float2 b = *(const float2*)&Bs[buf][k][tx * 2];
            unsigned long long bb0 = f2pack(b.x, b.x);
            unsigned long long bb1 = f2pack(b.y, b.y);
            const ulonglong2* ap = (const ulonglong2*)&As[buf][k][ty * 8];
            ulonglong2 a01 = ap[0];
            ulonglong2 a23 = ap[1];
            f2fma(acc2[0][0], a01.x, bb0); f2fma(acc2[0][1], a01.x, bb1);
            f2fma(acc2[1][0], a01.y, bb0); f2fma(acc2[1][1], a01.y, bb1);
            f2fma(acc2[2][0], a23.x, bb0); f2fma(acc2[2][1], a23.x, bb1);
            f2fma(acc2[3][0], a23.y, bb0); f2fma(acc2[3][1], a23.y, bb1);
        }
        int ke = kt + 32;
        if ((ke % KC) == 0 || ke == K) { // ordered panel flush (bitwise R7)
            #pragma unroll
            for (int p = 0; p < 4; p++) {
                f2add(tot2[p][0], acc2[p][0]); acc2[p][0] = 0ull;
                f2add(tot2[p][1], acc2[p][1]); acc2[p][1] = 0ull;
            }
        }
        buf ^= 1;
    }
    float* Cg = C + (size_t)bm0 * N + bn0;
    #pragma unroll
    for (int p = 0; p < 4; p++) {
        float r0c0, r1c0, r0c1, r1c1;
        f2unpack(r0c0, r1c0, tot2[p][0]);
        f2unpack(r0c1, r1c1, tot2[p][1]);
        *(float2*)&Cg[(size_t)(ty * 8 + 2 * p) * N + tx * 2] = make_float2(r0c0, r0c1);
        *(float2*)&Cg[(size_t)(ty * 8 + 2 * p + 1) * N + tx * 2] = make_float2(r1c0, r1c1);
    }
}

// ------------------------------- LIF scan ----------------------------------
__global__ void lifscan_k(const float* __restrict__ part, int S,
                          size_t pstride, size_t tstride,
                          const float* __restrict__ cn,
                          const float* __restrict__ tn,
                          const float* __restrict__ th,
                          const float* __restrict__ wn,
                          float* __restrict__ sall,
                          float* __restrict__ out,
                          int N) {
    int i = blockIdx.x * 256 + threadIdx.x;
    int n = i % N;
    size_t sz = (size_t)BSZ * N;
    float wnv = wn[n], thb = th[n];
    float sc = __fmul_rn(0.05f, wnv);

    float curbase = 0.f;
    if (tstride == 0) {
        curbase = __fadd_rn(0.f, part[i]);
        for (int s = 1; s < S; s++)
            curbase = __fadd_rn(curbase, part[(size_t)s * pstride + i]);
    }

    float V = 0.f, ls = -1e9f;
    float costs = 0.f;
    unsigned int cnt = 0u;

    for (int t = 1; t <= TT; t++) {
        size_t off = (size_t)(t - 1) * sz + i;
        float cur = (tstride == 0) ? curbase : part[(size_t)(t - 1) * tstride + i];
        float tf = (float)t;
        cur = __fmaf_rn(cn[off], sc, cur);
        bool refrac = __fadd_rn(tf, -ls) < 2.0f;
        float Vcand = __fmaf_rn(0.95f, V, cur);
        float Vn = refrac ? V : Vcand;
        float thr = __fmaf_rn(tn[off], 0.1f, thb);
        bool sp = (!refrac) && (Vn > thr);
        V = sp ? 0.f : Vn;
        ls = sp ? tf : ls;
        float spf = sp ? 1.f : 0.f;
        if (sall) sall[off] = spf;
        if (out && t == TT) out[i] = spf;
        if (sp) {
            float cf = 0.01f * fminf(10.f, 17.f - tf);
            costs = __fadd_rn(costs, __fmul_rn(cf, wnv));
            cnt++;
        }
    }

    #pragma unroll
    for (int off = 16; off; off >>= 1) {
        costs += __shfl_down_sync(0xffffffffu, costs, off);
        cnt += __shfl_down_sync(0xffffffffu, cnt, off);
    }
    __shared__ float shc[8];
    __shared__ unsigned int shs[8];
    if ((threadIdx.x & 31) == 0) { shc[threadIdx.x >> 5] = costs; shs[threadIdx.x >> 5] = cnt; }
    __syncthreads();
    if (threadIdx.x == 0) {
        float tc = 0.f; unsigned int ts = 0u;
        #pragma unroll
        for (int k = 0; k < 8; k++) { tc += shc[k]; ts += shs[k]; }
        atomicAdd(&g_cost, (double)tc);
        atomicAdd(&g_tot, ts);
    }
}

// ------------------------------- finalize -----------------------------------
__global__ void final_k(float* out, int out_size) {
    float cost = (float)g_cost;
    float p1 = __fdiv_rn((float)g_tot, 14680064.f);
    float p0 = __fadd_rn(1.f, -p1);
    float ent = -(p1 * log2f(p1 + 1e-12f) + p0 * log2f(p0 + 1e-12f));
    if (out_size >= BSZ * N3 + 2) {
        out[BSZ * N3] = cost;
        out[BSZ * N3 + 1] = ent;
    } else if (out_size >= 2) {
        out[out_size - 2] = cost;
        out[out_size - 1] = ent;
    }
}

// ------------------------------- launch -------------------------------------
extern "C" void kernel_launch(void* const* d_in, const int* in_sizes, int n_in,
                              void* d_out, int out_size) {
    const float *inputs, *w0, *w1, *w2, *th0, *th1, *th2;
    const float *cn0, *cn1, *cn2, *tn0, *tn1, *tn2;
    inputs = (const float*)d_in[0];
    if (in_sizes[2] == 2048) {
        w0 = (const float*)d_in[1];  th0 = (const float*)d_in[2];
        cn0 = (const float*)d_in[3]; tn0 = (const float*)d_in[4];
        w1 = (const float*)d_in[5];  th1 = (const float*)d_in[6];
        cn1 = (const float*)d_in[7]; tn1 = (const float*)d_in[8];
        w2 = (const float*)d_in[9];  th2 = (const float*)d_in[10];
        cn2 = (const float*)d_in[11]; tn2 = (const float*)d_in[12];
    } else {
        w0 = (const float*)d_in[1];  w1 = (const float*)d_in[2];  w2 = (const float*)d_in[3];
        th0 = (const float*)d_in[4]; th1 = (const float*)d_in[5]; th2 = (const float*)d_in[6];
        cn0 = (const float*)d_in[7]; cn1 = (const float*)d_in[8]; cn2 = (const float*)d_in[9];
        tn0 = (const float*)d_in[10]; tn1 = (const float*)d_in[11]; tn2 = (const float*)d_in[12];
    }
    float* out = (float*)d_out;

    void *pI0p, *ps0, *pc1, *ps1, *pc2, *pwn0, *pwn1, *pwn2;
    cudaGetSymbolAddress(&pI0p, g_I0p);
    cudaGetSymbolAddress(&ps0, g_s0);
    cudaGetSymbolAddress(&pc1, g_c1);
    cudaGetSymbolAddress(&ps1, g_s1);
    cudaGetSymbolAddress(&pc2, g_c2);
    cudaGetSymbolAddress(&pwn0, g_wn0);
    cudaGetSymbolAddress(&pwn1, g_wn1);
    cudaGetSymbolAddress(&pwn2, g_wn2);

    const int NP1 = (N0 + KC - 1) / KC;  // 4 panels (K=1024)

    // Launch order chosen so ncu's "-s 5 -c 1" capture window lands on
    // gemmf (launch #6) instead of a wnorm — dependency-legal reordering.
    init_k<<<1, 32>>>();                                              // 1
    wnorm_k<<<N1 / 8, 256>>>(w0, N0, N1, (float*)pwn0);               // 2
    gemm0_k<<<dim3(N1 / 64, BSZ / 64, NP1), 256>>>(inputs, w0,        // 3
                                                   (float*)pI0p, BSZ, N1, N0);
    lifscan_k<<<BSZ * N1 / 256, 256>>>((const float*)pI0p, NP1,       // 4
                                       (size_t)BSZ * N1, 0,
                                       cn0, tn0, th0, (const float*)pwn0,
                                       (float*)ps0, nullptr, N1);
    wnorm_k<<<N2 / 8, 256>>>(w1, N1, N2, (float*)pwn1);               // 5
    gemmf_k<<<dim3(N2 / 64, MB / 64), 256>>>((const float*)ps0, w1,   // 6 <- ncu
                                             (float*)pc1, MB, N2, N1);
    lifscan_k<<<BSZ * N2 / 256, 256>>>((const float*)pc1, 1, 0,
                                       (size_t)BSZ * N2,
                                       cn1, tn1, th1, (const float*)pwn1,
                                       (float*)ps1, nullptr, N2);
    wnorm_k<<<N3 / 8, 256>>>(w2, N2, N3, (float*)pwn2);
    gemmf_k<<<dim3(N3 / 64, MB / 64), 256>>>((const float*)ps1, w2,
                                             (float*)pc2, MB, N3, N2);
    lifscan_k<<<BSZ * N3 / 256, 256>>>((const float*)pc2, 1, 0,
                                       (size_t)BSZ * N3,
                                       cn2, tn2, th2, (const float*)pwn2,
                                       nullptr, out, N3);
    final_k<<<1, 1>>>(out, out_size);
}

// round 16
// speedup vs baseline: 1.1474x; 1.1474x over previous
#include <cuda_runtime.h>
#include <cuda_bf16.h>
#include <math.h>
#include <stdint.h>

#define BSZ 256
#define N0 1024
#define N1 2048
#define N2 1024
#define N3 512
#define TT 16
#define KC 320          // Eigen MT gebp depth-blocking (validated bit-exact R7-R15)
#define MB (TT * BSZ)   // 4096 batched rows

// ------------------------- device scratch (static) -------------------------
__device__ __align__(16) float g_I0p[4 * BSZ * N1];   // I0 panel partials (layer0 only)
__device__ __align__(16) float g_s0[MB * N1];         // spikes L0, all steps
__device__ __align__(16) float g_c1[MB * N2];         // L1 currents
__device__ __align__(16) float g_s1[MB * N2];         // spikes L1, all steps
__device__ __align__(16) float g_c2[MB * N3];         // L2 currents
__device__ float g_wn0[N1], g_wn1[N2], g_wn2[N3];
__device__ double g_cost;
__device__ unsigned int g_tot;

// ------------------------- f32x2 packed helpers ----------------------------
__device__ __forceinline__ unsigned long long f2pack(float x, float y) {
    unsigned long long r;
    asm("mov.b64 %0, {%1, %2};" : "=l"(r) : "f"(x), "f"(y));
    return r;
}
__device__ __forceinline__ void f2fma(unsigned long long& d,
                                      unsigned long long a, unsigned long long b) {
    asm("fma.rn.f32x2 %0, %1, %2, %0;" : "+l"(d) : "l"(a), "l"(b));
}
__device__ __forceinline__ void f2add(unsigned long long& d, unsigned long long a) {
    asm("add.rn.f32x2 %0, %1, %0;" : "+l"(d) : "l"(a));
}
__device__ __forceinline__ void f2unpack(float& x, float& y, unsigned long long v) {
    asm("mov.b64 {%0, %1}, %2;" : "=f"(x), "=f"(y) : "l"(v));
}

// ------------------------------- init --------------------------------------
__global__ void init_k() {
    if (threadIdx.x == 0) { g_cost = 0.0; g_tot = 0u; }
}

// ---- per-row weight norms: warp per row, coalesced, tree reduce ------------
__global__ void wnorm_k(const float* __restrict__ w, int K, int Nrows,
                        float* __restrict__ o) {
    int row = blockIdx.x * 8 + (threadIdx.x >> 5);
    int lane = threadIdx.x & 31;
    if (row >= Nrows) return;
    const float* wr = w + (size_t)row * K;
    float s = 0.f;
    for (int j = lane; j < K; j += 32) {
        float v = wr[j];
        s = __fadd_rn(s, __fmul_rn(v, v));
    }
    #pragma unroll
    for (int off = 16; off; off >>= 1)
        s = __fadd_rn(s, __shfl_down_sync(0xffffffffu, s, off));
    if (lane == 0) o[row] = sqrtf(s);
}

// -------------------- GEMM, split-K form (layer-0 only) ---------------------
// Validated R9-R15. P[z,m,n] = strict ascending-k FMA chain over panel z.
__global__ void __launch_bounds__(256) gemm0_k(const float* __restrict__ A,
                                               const float* __restrict__ Bm,
                                               float* __restrict__ P,
                                               int M, int N, int K) {
    __shared__ float As[16][68];
    __shared__ float Bs[16][68];
    const int bn0 = blockIdx.x * 64, bm0 = blockIdx.y * 64;
    const int k0 = blockIdx.z * KC;
    const int kchunk = min(KC, K - k0);
    const int tid = threadIdx.x;
    const int tx = tid & 31, ty = tid >> 5;
    const float* Ag = A + (size_t)bm0 * K + k0;
    const float* Bg = Bm + (size_t)bn0 * K + k0;

    unsigned long long acc2[4][2];
    #pragma unroll
    for (int p = 0; p < 4; p++) { acc2[p][0] = 0ull; acc2[p][1] = 0ull; }

    const int arow = tid >> 2, akq = (tid & 3) * 4;
    float4 ra = *(const float4*)(Ag + (size_t)arow * K + akq);
    float4 rb = *(const float4*)(Bg + (size_t)arow * K + akq);

    for (int kt = 0; kt < kchunk; kt += 16) {
        As[akq + 0][arow] = ra.x; As[akq + 1][arow] = ra.y;
        As[akq + 2][arow] = ra.z; As[akq + 3][arow] = ra.w;
        Bs[akq + 0][arow] = rb.x; Bs[akq + 1][arow] = rb.y;
        Bs[akq + 2][arow] = rb.z; Bs[akq + 3][arow] = rb.w;
        __syncthreads();
        int kn = kt + 16;
        if (kn < kchunk) {
            ra = *(const float4*)(Ag + (size_t)arow * K + kn + akq);
            rb = *(const float4*)(Bg + (size_t)arow * K + kn + akq);
        }
        #pragma unroll
        for (int k = 0; k < 16; k++) {
            float2 b = *(const float2*)&Bs[k][tx * 2];
            unsigned long long bb0 = f2pack(b.x, b.x);
            unsigned long long bb1 = f2pack(b.y, b.y);
            const ulonglong2* ap = (const ulonglong2*)&As[k][ty * 8];
            ulonglong2 a01 = ap[0];
            ulonglong2 a23 = ap[1];
            f2fma(acc2[0][0], a01.x, bb0); f2fma(acc2[0][1], a01.x, bb1);
            f2fma(acc2[1][0], a01.y, bb0); f2fma(acc2[1][1], a01.y, bb1);
            f2fma(acc2[2][0], a23.x, bb0); f2fma(acc2[2][1], a23.x, bb1);
            f2fma(acc2[3][0], a23.y, bb0); f2fma(acc2[3][1], a23.y, bb1);
        }
        __syncthreads();
    }
    float* Pg = P + (size_t)blockIdx.z * M * N + (size_t)bm0 * N + bn0;
    #pragma unroll
    for (int p = 0; p < 4; p++) {
        float r0c0, r1c0, r0c1, r1c1;
        f2unpack(r0c0, r1c0, acc2[p][0]);
        f2unpack(r0c1, r1c1, acc2[p][1]);
        *(float2*)&Pg[(size_t)(ty * 8 + 2 * p) * N + tx * 2] = make_float2(r0c0, r0c1);
        *(float2*)&Pg[(size_t)(ty * 8 + 2 * p + 1) * N + tx * 2] = make_float2(r1c0, r1c1);
    }
}

// ---- GEMM, full-K, kc=320 panels, 2-stage smem, BK=16, 4m x 4n micro-tile --
// Same loads/barrier structure as R14 (693us validated). Single change:
// thread micro-tile 8m x 2n -> 4m x 4n (tx:16 n-groups of 4 cols, ty:16
// m-groups of 4 rows). Cuts per-warp-k-iter LDS crossbar cycles 4 -> 3
// (A: one LDS.128, 2 distinct addrs; B: one LDS.128, 16 distinct).
// Per-output ascending-k FMA chains + kc flush unchanged -> bit-exact.
__global__ void __launch_bounds__(256) gemmf_k(const float* __restrict__ A,
                                               const float* __restrict__ Bm,
                                               float* __restrict__ C,
                                               int M, int N, int K) {
    __shared__ float As[2][16][68];
    __shared__ float Bs[2][16][68];

    const int bn0 = blockIdx.x * 64, bm0 = blockIdx.y * 64;
    const int tid = threadIdx.x;
    const int tx = tid & 15, ty = tid >> 4;      // 16 n-groups x 16 m-groups

    const float* Ag = A + (size_t)bm0 * K;
    const float* Bg = Bm + (size_t)bn0 * K;

    unsigned long long acc2[2][4], tot2[2][4];   // 2 row-pairs x 4 cols
    #pragma unroll
    for (int p = 0; p < 2; p++)
        #pragma unroll
        for (int c = 0; c < 4; c++) { acc2[p][c] = 0ull; tot2[p][c] = 0ull; }

    const int arow = tid >> 2, akq = (tid & 3) * 4;
    float4 ra = *(const float4*)(Ag + (size_t)arow * K + akq);
    float4 rb = *(const float4*)(Bg + (size_t)arow * K + akq);

    int buf = 0;
    for (int kt = 0; kt < K; kt += 16) {
        As[buf][akq + 0][arow] = ra.x; As[buf][akq + 1][arow] = ra.y;
        As[buf][akq + 2][arow] = ra.z; As[buf][akq + 3][arow] = ra.w;
        Bs[buf][akq + 0][arow] = rb.x; Bs[buf][akq + 1][arow] = rb.y;
        Bs[buf][akq + 2][arow] = rb.z; Bs[buf][akq + 3][arow] = rb.w;
        __syncthreads();                 // single barrier per k-tile
        int kn = kt + 16;
        if (kn < K) {                    // next-tile loads fly during compute
            ra = *(const float4*)(Ag + (size_t)arow * K + kn + akq);
            rb = *(const float4*)(Bg + (size_t)arow * K + kn + akq);
        }
        #pragma unroll
        for (int k = 0; k < 16; k++) {
            float4 b = *(const float4*)&Bs[buf][k][tx * 4];
            unsigned long long bb0 = f2pack(b.x, b.x);
            unsigned long long bb1 = f2pack(b.y, b.y);
            unsigned long long bb2 = f2pack(b.z, b.z);
            unsigned long long bb3 = f2pack(b.w, b.w);
            ulonglong2 a = *(const ulonglong2*)&As[buf][k][ty * 4];
            // a.x = rows (4ty, 4ty+1), a.y = rows (4ty+2, 4ty+3)
            f2fma(acc2[0][0], a.x, bb0); f2fma(acc2[0][1], a.x, bb1);
            f2fma(acc2[0][2], a.x, bb2); f2fma(acc2[0][3], a.x, bb3);
            f2fma(acc2[1][0], a.y, bb0); f2fma(acc2[1][1], a.y, bb1);
            f2fma(acc2[1][2], a.y, bb2); f2fma(acc2[1][3], a.y, bb3);
        }
        int ke = kt + 16;
        if ((ke % KC) == 0 || ke == K) { // ordered panel flush (bitwise R7)
            #pragma unroll
            for (int p = 0; p < 2; p++)
                #pragma unroll
                for (int c = 0; c < 4; c++) {
                    f2add(tot2[p][c], acc2[p][c]);
                    acc2[p][c] = 0ull;
                }
        }
        buf ^= 1;
    }
    float* Cg = C + (size_t)bm0 * N + bn0;
    #pragma unroll
    for (int p = 0; p < 2; p++) {
        float r0[4], r1[4];
        #pragma unroll
        for (int c = 0; c < 4; c++) f2unpack(r0[c], r1[c], tot2[p][c]);
        *(float4*)&Cg[(size_t)(ty * 4 + 2 * p) * N + tx * 4] =
            make_float4(r0[0], r0[1], r0[2], r0[3]);
        *(float4*)&Cg[(size_t)(ty * 4 + 2 * p + 1) * N + tx * 4] =
            make_float4(r1[0], r1[1], r1[2], r1[3]);
    }
}

// ------------------------------- LIF scan ----------------------------------
__global__ void lifscan_k(const float* __restrict__ part, int S,
                          size_t pstride, size_t tstride,
                          const float* __restrict__ cn,
                          const float* __restrict__ tn,
                          const float* __restrict__ th,
                          const float* __restrict__ wn,
                          float* __restrict__ sall,
                          float* __restrict__ out,
                          int N) {
    int i = blockIdx.x * 256 + threadIdx.x;
    int n = i % N;
    size_t sz = (size_t)BSZ * N;
    float wnv = wn[n], thb = th[n];
    float sc = __fmul_rn(0.05f, wnv);

    float curbase = 0.f;
    if (tstride == 0) {
        curbase = __fadd_rn(0.f, part[i]);
        for (int s = 1; s < S; s++)
            curbase = __fadd_rn(curbase, part[(size_t)s * pstride + i]);
    }

    float V = 0.f, ls = -1e9f;
    float costs = 0.f;
    unsigned int cnt = 0u;

    for (int t = 1; t <= TT; t++) {
        size_t off = (size_t)(t - 1) * sz + i;
        float cur = (tstride == 0) ? curbase : part[(size_t)(t - 1) * tstride + i];
        float tf = (float)t;
        cur = __fmaf_rn(cn[off], sc, cur);
        bool refrac = __fadd_rn(tf, -ls) < 2.0f;
        float Vcand = __fmaf_rn(0.95f, V, cur);
        float Vn = refrac ? V : Vcand;
        float thr = __fmaf_rn(tn[off], 0.1f, thb);
        bool sp = (!refrac) && (Vn > thr);
        V = sp ? 0.f : Vn;
        ls = sp ? tf : ls;
        float spf = sp ? 1.f : 0.f;
        if (sall) sall[off] = spf;
        if (out && t == TT) out[i] = spf;
        if (sp) {
            float cf = 0.01f * fminf(10.f, 17.f - tf);
            costs = __fadd_rn(costs, __fmul_rn(cf, wnv));
            cnt++;
        }
    }

    #pragma unroll
    for (int off = 16; off; off >>= 1) {
        costs += __shfl_down_sync(0xffffffffu, costs, off);
        cnt += __shfl_down_sync(0xffffffffu, cnt, off);
    }
    __shared__ float shc[8];
    __shared__ unsigned int shs[8];
    if ((threadIdx.x & 31) == 0) { shc[threadIdx.x >> 5] = costs; shs[threadIdx.x >> 5] = cnt; }
    __syncthreads();
    if (threadIdx.x == 0) {
        float tc = 0.f; unsigned int ts = 0u;
        #pragma unroll
        for (int k = 0; k < 8; k++) { tc += shc[k]; ts += shs[k]; }
        atomicAdd(&g_cost, (double)tc);
        atomicAdd(&g_tot, ts);
    }
}

// ------------------------------- finalize -----------------------------------
__global__ void final_k(float* out, int out_size) {
    float cost = (float)g_cost;
    float p1 = __fdiv_rn((float)g_tot, 14680064.f);
    float p0 = __fadd_rn(1.f, -p1);
    float ent = -(p1 * log2f(p1 + 1e-12f) + p0 * log2f(p0 + 1e-12f));
    if (out_size >= BSZ * N3 + 2) {
        out[BSZ * N3] = cost;
        out[BSZ * N3 + 1] = ent;
    } else if (out_size >= 2) {
        out[out_size - 2] = cost;
        out[out_size - 1] = ent;
    }
}

// ------------------------------- launch -------------------------------------
extern "C" void kernel_launch(void* const* d_in, const int* in_sizes, int n_in,
                              void* d_out, int out_size) {
    const float *inputs, *w0, *w1, *w2, *th0, *th1, *th2;
    const float *cn0, *cn1, *cn2, *tn0, *tn1, *tn2;
    inputs = (const float*)d_in[0];
    if (in_sizes[2] == 2048) {
        w0 = (const float*)d_in[1];  th0 = (const float*)d_in[2];
        cn0 = (const float*)d_in[3]; tn0 = (const float*)d_in[4];
        w1 = (const float*)d_in[5];  th1 = (const float*)d_in[6];
        cn1 = (const float*)d_in[7]; tn1 = (const float*)d_in[8];
        w2 = (const float*)d_in[9];  th2 = (const float*)d_in[10];
        cn2 = (const float*)d_in[11]; tn2 = (const float*)d_in[12];
    } else {
        w0 = (const float*)d_in[1];  w1 = (const float*)d_in[2];  w2 = (const float*)d_in[3];
        th0 = (const float*)d_in[4]; th1 = (const float*)d_in[5]; th2 = (const float*)d_in[6];
        cn0 = (const float*)d_in[7]; cn1 = (const float*)d_in[8]; cn2 = (const float*)d_in[9];
        tn0 = (const float*)d_in[10]; tn1 = (const float*)d_in[11]; tn2 = (const float*)d_in[12];
    }
    float* out = (float*)d_out;

    void *pI0p, *ps0, *pc1, *ps1, *pc2, *pwn0, *pwn1, *pwn2;
    cudaGetSymbolAddress(&pI0p, g_I0p);
    cudaGetSymbolAddress(&ps0, g_s0);
    cudaGetSymbolAddress(&pc1, g_c1);
    cudaGetSymbolAddress(&ps1, g_s1);
    cudaGetSymbolAddress(&pc2, g_c2);
    cudaGetSymbolAddress(&pwn0, g_wn0);
    cudaGetSymbolAddress(&pwn1, g_wn1);
    cudaGetSymbolAddress(&pwn2, g_wn2);

    const int NP1 = (N0 + KC - 1) / KC;  // 4 panels (K=1024)

    init_k<<<1, 32>>>();
    wnorm_k<<<N1 / 8, 256>>>(w0, N0, N1, (float*)pwn0);
    gemm0_k<<<dim3(N1 / 64, BSZ / 64, NP1), 256>>>(inputs, w0,
                                                   (float*)pI0p, BSZ, N1, N0);
    lifscan_k<<<BSZ * N1 / 256, 256>>>((const float*)pI0p, NP1,
                                       (size_t)BSZ * N1, 0,
                                       cn0, tn0, th0, (const float*)pwn0,
                                       (float*)ps0, nullptr, N1);
    wnorm_k<<<N2 / 8, 256>>>(w1, N1, N2, (float*)pwn1);
    gemmf_k<<<dim3(N2 / 64, MB / 64), 256>>>((const float*)ps0, w1,
                                             (float*)pc1, MB, N2, N1);
    lifscan_k<<<BSZ * N2 / 256, 256>>>((const float*)pc1, 1, 0,
                                       (size_t)BSZ * N2,
                                       cn1, tn1, th1, (const float*)pwn1,
                                       (float*)ps1, nullptr, N2);
    wnorm_k<<<N3 / 8, 256>>>(w2, N2, N3, (float*)pwn2);
    gemmf_k<<<dim3(N3 / 64, MB / 64), 256>>>((const float*)ps1, w2,
                                             (float*)pc2, MB, N3, N2);
    lifscan_k<<<BSZ * N3 / 256, 256>>>((const float*)pc2, 1, 0,
                                       (size_t)BSZ * N3,
                                       cn2, tn2, th2, (const float*)pwn2,
                                       nullptr, out, N3);
    final_k<<<1, 1>>>(out, out_size);
}